// round 12
// baseline (speedup 1.0000x reference)
#include <cuda_runtime.h>
#include <math.h>

#define NS_   6
#define NT_   4
#define B_    2
#define N_    32
#define H_    768
#define W_    768
#define ROI_  28
#define C_    10           // NS + NT
#define L_    39           // 1 + NS + N
#define NEGV  (-100.0f)

#define SEAM_TOT (B_ * H_ * W_)                 // 1179648
#define FULL_OUT (SEAM_TOT + 2 * B_ * L_ + B_)  // 1179806
#define LUTN  (NS_ + N_)                        // 38
#define HW_   (H_ * W_)

// Scratch: zero-initialized at module load; k_post re-zeroes hist/cstuff after
// consuming them, so every graph replay starts clean (self-cleaning pipeline).
__device__ int g_hist[B_ * N_ * C_];
__device__ int g_cstuff[B_ * NS_];
__device__ __align__(16) unsigned char g_pp[B_ * H_ * W_];
__device__ float g_lutf[B_ * LUTN];

// XLA logistic_expander form: 1 / (1 + exp(-x)). sigmoid(-100) == 0 exactly.
__device__ __forceinline__ float jsig(float x) {
    return __fdiv_rn(1.0f, __fadd_rn(1.0f, expf(-x)));
}

__device__ __forceinline__ float f4c(const float4 v, int j) {
    return (j == 0) ? v.x : (j == 1) ? v.y : (j == 2) ? v.z : v.w;
}

// warp-aggregated shared-hist add: uniform fast path, match_any fallback
__device__ __forceinline__ void hist_add(int key, int lane,
                                         int* sh_hist, int* sh_cst) {
    const unsigned FULL = 0xffffffffu;
    int k0 = __shfl_sync(FULL, key, 0);
    if (__all_sync(FULL, key == k0)) {
        if (lane == 0) {
            if (k0 >= 64) atomicAdd(&sh_hist[k0 - 64], 32);
            else          atomicAdd(&sh_cst[k0], 32);
        }
    } else {
        unsigned mm = __match_any_sync(FULL, key);
        if (lane == __ffs(mm) - 1) {
            int cnt = __popc(mm);
            if (key >= 64) atomicAdd(&sh_hist[key - 64], cnt);
            else           atomicAdd(&sh_cst[key], cnt);
        }
    }
}

// ---- kernel 1: fused per-pixel argmax + histograms -------------------------
// One block per (row, batch); 192 threads x 4 consecutive px via float4 loads
// (6 LDG.128 stuff, +4 LDG.128 thing on slow path only). Row-active instances
// compacted; per-warp ballot narrows to instances meeting the warp's 128-px
// window. Non-covering instances contribute C_OUT = -0.0 exactly (gap logic
// preserves argmax-first ordering). Tree argmax (first-max semantics). Hybrid
// warp-aggregated histograms with a 128-px-uniform single-atomic path.
__global__ void __launch_bounds__(192, 5)
k_main(const float* __restrict__ sem, const float* __restrict__ roi,
       const float* __restrict__ bbx, const int* __restrict__ cls) {
    const unsigned FULL = 0xffffffffu;
    const int y = blockIdx.x;
    const int b = blockIdx.y;
    const int t = threadIdx.x;
    const int lane = t & 31;

    __shared__ int sh_hist[N_ * C_];
    __shared__ int sh_cst[NS_];
    __shared__ int sh_K;
    __shared__ int sa_n[N_], sa_x0[N_], sa_x1r[N_], sa_xs[N_], sa_xe[N_];
    __shared__ int sa_inYm[N_], sa_cls[N_], sa_r0[N_], sa_r1[N_];
    __shared__ float sa_wy[N_], sa_rx[N_];

    for (int i = t; i < N_ * C_; i += 192) sh_hist[i] = 0;
    if (t < NS_) sh_cst[t] = 0;

    if (t < 32) {
        const float* bb = bbx + (b * N_ + t) * 4;
        float y0f = bb[0], x0f = bb[1], y1f = bb[2], x1f = bb[3];
        int y0 = (int)floorf(y0f), x0 = (int)floorf(x0f);
        int y1 = (int)floorf(y1f), x1 = (int)floorf(x1f);
        int y1r = (int)(rintf(y1f) + 1.0f);   // round-half-even like jnp.round
        int x1r = (int)(rintf(x1f) + 1.0f);
        int hi = y1 - y0 + 1; if (hi < 1) hi = 1;
        int wi = x1 - x0 + 1; if (wi < 1) wi = 1;
        int ys = max(y0, 0), ye = min(y1 + 1, H_);
        float ry = __fdiv_rn(28.0f, (float)hi);
        float rx = __fdiv_rn(28.0f, (float)wi);
        int c = cls[b * N_ + t];
        int mskoff = ((b * N_ + t) * NT_ + c) * ROI_ * ROI_;

        bool inYs = (y >= y0) && (y < y1r);
        unsigned mask = __ballot_sync(FULL, inYs);
        if (t == 0) sh_K = __popc(mask);
        if (inYs) {
            int slot = __popc(mask & ((1u << t) - 1u));
            sa_n[slot] = t;
            sa_x0[slot] = x0; sa_x1r[slot] = x1r;
            sa_xs[slot] = max(x0, 0); sa_xe[slot] = min(x1 + 1, W_);
            sa_cls[slot] = c; sa_rx[slot] = rx;
            int inYm = (y >= ys) && (y < ye);
            sa_inYm[slot] = inYm;
            if (inYm) {
                float sy = __fsub_rn(
                    __fmul_rn(__fadd_rn(__fsub_rn((float)y, (float)y0), 0.5f), ry),
                    0.5f);
                sy = fminf(fmaxf(sy, 0.0f), 27.0f);
                float fiy0 = floorf(sy);
                int iy0 = (int)fiy0;
                int iy1 = min(iy0 + 1, ROI_ - 1);
                sa_wy[slot] = __fsub_rn(sy, fiy0);
                sa_r0[slot] = mskoff + iy0 * ROI_;
                sa_r1[slot] = mskoff + iy1 * ROI_;
            } else {
                sa_wy[slot] = 0.0f; sa_r0[slot] = 0; sa_r1[slot] = 0;
            }
        }
    }
    __syncthreads();

    const int K = sh_K;
    const float C_OUT = -0.0f;
    const float* semb0 = sem + (size_t)b * (C_ * HW_) + (size_t)y * W_;

    // warp filter: instances whose strict x-interval meets this warp's
    // 128-pixel window [warp*128, warp*128+128)
    unsigned wmask;
    {
        int wlo = (t & ~31) * 4;
        bool inter = false;
        if (lane < K) inter = (sa_x0[lane] <= wlo + 127) && (sa_x1r[lane] > wlo);
        wmask = __ballot_sync(FULL, inter);
    }

    // stuff channels, 4 px per thread, front-batched LDG.128
    float4 sc[NS_];
#pragma unroll
    for (int c = 0; c < NS_; c++)
        sc[c] = __ldg((const float4*)(semb0 + (size_t)c * HW_) + t);

    // per-pixel tree argmax over stuff (first-max: right wins on strict >)
    float best[4]; int bi[4];
#pragma unroll
    for (int j = 0; j < 4; j++) {
        float s0 = f4c(sc[0], j), s1 = f4c(sc[1], j), s2 = f4c(sc[2], j);
        float s3 = f4c(sc[3], j), s4 = f4c(sc[4], j), s5 = f4c(sc[5], j);
        int   i01 = (s1 > s0) ? 1 : 0;       float v01 = (s1 > s0) ? s1 : s0;
        int   i23 = (s3 > s2) ? 3 : 2;       float v23 = (s3 > s2) ? s3 : s2;
        int   i45 = (s5 > s4) ? 5 : 4;       float v45 = (s5 > s4) ? s5 : s4;
        int   i03 = (v23 > v01) ? i23 : i01; float v03 = (v23 > v01) ? v23 : v01;
        bi[j]   = (v45 > v03) ? i45 : i03;
        best[j] = (v45 > v03) ? v45 : v03;
    }

    bool anyneg = (best[0] < 0.0f) || (best[1] < 0.0f) ||
                  (best[2] < 0.0f) || (best[3] < 0.0f);
    bool slow = (wmask != 0) || __any_sync(FULL, anyneg);

    int key[4];
    if (!slow) {
#pragma unroll
        for (int j = 0; j < 4; j++) key[j] = bi[j];
    } else {
        // thing channels
        float4 th[NT_];
#pragma unroll
        for (int c = 0; c < NT_; c++)
            th[c] = __ldg((const float4*)(semb0 + (size_t)(NS_ + c) * HW_) + t);

#pragma unroll
        for (int j = 0; j < 4; j++) {
            const int x = t * 4 + j;
            float s6 = f4c(th[0], j), s7 = f4c(th[1], j);
            float s8 = f4c(th[2], j), s9 = f4c(th[3], j);
            int   i67 = (s7 > s6) ? 7 : 6;       float v67 = (s7 > s6) ? s7 : s6;
            int   i89 = (s9 > s8) ? 9 : 8;       float v89 = (s9 > s8) ? s9 : s8;
            int   i69 = (v89 > v67) ? i89 : i67; float v69 = (v89 > v67) ? v89 : v67;
            int   sem_pred = (v69 > best[j]) ? i69 : bi[j];
            float bb = best[j]; int bb_i = bi[j];

            int nextn = 0;
            for (unsigned mrem = wmask; mrem; mrem &= mrem - 1) {
                int k = __ffs(mrem) - 1;
                int n = sa_n[k];
                if (n > nextn && bb < 0.0f) { bb = C_OUT; bb_i = NS_ + nextn; }
                nextn = n + 1;

                float v;
                bool sxin = (x >= sa_x0[k]) && (x < sa_x1r[k]);
                if (!sxin) {
                    v = C_OUT;
                } else {
                    int ck = sa_cls[k];
                    float a = (ck == 0) ? s6 : (ck == 1) ? s7 : (ck == 2) ? s8 : s9;
                    float m;
                    bool mxin = sa_inYm[k] && (x >= sa_xs[k]) && (x < sa_xe[k]);
                    if (mxin) {
                        float sx = __fsub_rn(
                            __fmul_rn(__fadd_rn(__fsub_rn((float)x, (float)sa_x0[k]), 0.5f),
                                      sa_rx[k]),
                            0.5f);
                        sx = fminf(fmaxf(sx, 0.0f), 27.0f);
                        float fix0 = floorf(sx);
                        int ix0 = (int)fix0;
                        int ix1 = min(ix0 + 1, ROI_ - 1);
                        float wx = __fsub_rn(sx, fix0);
                        const float* r0 = roi + sa_r0[k];
                        const float* r1 = roi + sa_r1[k];
                        float wy = sa_wy[k];
                        float omy = __fsub_rn(1.0f, wy);
                        float c0 = __fadd_rn(__fmul_rn(__ldg(r0 + ix0), omy),
                                             __fmul_rn(__ldg(r1 + ix0), wy));
                        float c1 = __fadd_rn(__fmul_rn(__ldg(r0 + ix1), omy),
                                             __fmul_rn(__ldg(r1 + ix1), wy));
                        float omx = __fsub_rn(1.0f, wx);
                        m = __fadd_rn(__fmul_rn(c0, omx), __fmul_rn(c1, wx));
                    } else {
                        m = NEGV;
                    }
                    v = __fmul_rn(__fadd_rn(jsig(a), jsig(m)), __fadd_rn(a, m));
                }
                if (v > bb) { bb = v; bb_i = NS_ + n; }
            }
            if (nextn < N_ && bb < 0.0f) { bb = C_OUT; bb_i = NS_ + nextn; }

            bi[j] = bb_i;
            key[j] = (bb_i >= NS_) ? (64 + (bb_i - NS_) * C_ + sem_pred) : bb_i;
        }
    }

    // packed pixel-label store (4 px -> one 32-bit store)
    uchar4 pk;
    pk.x = (unsigned char)bi[0]; pk.y = (unsigned char)bi[1];
    pk.z = (unsigned char)bi[2]; pk.w = (unsigned char)bi[3];
    ((uchar4*)g_pp)[((size_t)b * H_ + y) * (W_ / 4) + t] = pk;

    // histogram: 128-px-uniform single atomic, else per-px warp aggregation
    {
        int k0 = __shfl_sync(FULL, key[0], 0);
        bool uni = (key[0] == k0) && (key[1] == k0) &&
                   (key[2] == k0) && (key[3] == k0);
        if (__all_sync(FULL, uni)) {
            if (lane == 0) {
                if (k0 >= 64) atomicAdd(&sh_hist[k0 - 64], 128);
                else          atomicAdd(&sh_cst[k0], 128);
            }
        } else {
#pragma unroll
            for (int j = 0; j < 4; j++) hist_add(key[j], lane, sh_hist, sh_cst);
        }
    }
    __syncthreads();

    for (int i = t; i < N_ * C_; i += 192) {
        int v = sh_hist[i];
        if (v) atomicAdd(&g_hist[b * N_ * C_ + i], v);
    }
    if (t < NS_) {
        int v = sh_cst[t];
        if (v) atomicAdd(&g_cstuff[b * NS_ + t], v);
    }
}

// ---- kernel 2: warp-parallel relabel + small outputs; self-cleans scratch --
__global__ void __launch_bounds__(64)
k_post(const int* __restrict__ cls, float* __restrict__ out, int out_size) {
    const unsigned FULL = 0xffffffffu;
    int b = threadIdx.x >> 5;
    int lane = threadIdx.x & 31;
    int* hist = g_hist + (b * N_ + lane) * C_;

    int tot = 0, mc = 0, smax = 0;
#pragma unroll
    for (int c = 0; c < C_; c++) {
        int h = hist[c];
        tot += h;
        if (h > mc) { mc = h; smax = c; }
    }
    int pres = (tot > 0);
    int tmp = cls[b * N_ + lane] + NS_;
    int br1 = (smax == tmp);
    int br2 = (!br1) && (2 * mc >= tot) && (smax < NS_) && pres;
    int semlab = br2 ? smax : tmp;
    int kept = pres && !br2;

    int sp[NS_];
#pragma unroll
    for (int c = 0; c < NS_; c++) {
        int v = (semlab == c) ? tot : 0;
#pragma unroll
        for (int off = 16; off; off >>= 1) v += __shfl_down_sync(FULL, v, off);
        v = __shfl_sync(FULL, v, 0);
        sp[c] = g_cstuff[b * NS_ + c] + v;
    }

    int srank[NS_], nst = 0;
#pragma unroll
    for (int c = 0; c < NS_; c++) { if (sp[c] > 0) nst++; srank[c] = nst - 1; }

    unsigned kb = __ballot_sync(FULL, kept);
    int rank_k = __popc(kb & ((1u << lane) - 1u));
    int rk = __popc(kb);

    float* lut = g_lutf + b * LUTN;
    if (lane < NS_) lut[lane] = (float)(srank[lane] + 1);
    int lv = kept ? (1 + nst + rank_k)
                  : ((semlab < NS_) ? (srank[semlab] + 1) : 0);
    lut[NS_ + lane] = (float)lv;

    if (out_size >= FULL_OUT) {
        float* pcls = out + SEAM_TOT + b * L_;
        float* pisc = out + SEAM_TOT + B_ * L_ + b * L_;
        pcls[lane] = -1.0f;
        if (lane < L_ - 32) pcls[32 + lane] = -1.0f;
        __syncwarp(FULL);
        if (lane == 0) pcls[0] = 255.0f;
        if (lane < NS_ && sp[lane] > 0) pcls[1 + srank[lane]] = (float)lane;
        if (kept) pcls[1 + nst + rank_k] = (float)tmp;
        int vl = 1 + nst + rk;
        pisc[lane] = (lane < vl) ? 0.0f : -1.0f;
        if (lane < L_ - 32) pisc[32 + lane] = ((32 + lane) < vl) ? 0.0f : -1.0f;
        if (lane == 0) out[SEAM_TOT + 2 * B_ * L_ + b] = (float)vl;
    }
    // zero any residual output beyond the defined region (usually empty loop)
    for (int i = FULL_OUT + threadIdx.x; i < out_size; i += 64) out[i] = 0.0f;

    // self-clean scratch for the next graph replay
#pragma unroll
    for (int c = 0; c < C_; c++) hist[c] = 0;
    if (lane < NS_) g_cstuff[b * NS_ + lane] = 0;
}

// ---- kernel 3: LUT remap; shared LUT, 1 quad/thread, 1152 blocks -----------
__global__ void __launch_bounds__(256)
k_out(float* __restrict__ out) {
    __shared__ float lut[B_ * LUTN];
    int t = threadIdx.x;
    if (t < B_ * LUTN) lut[t] = g_lutf[t];
    __syncthreads();
    int i = blockIdx.x * 256 + t;              // quad index
    const int HWQ = HW_ / 4;
    unsigned int p = ((const unsigned int*)g_pp)[i];
    const float* l = lut + ((i >= HWQ) ? LUTN : 0);
    float4 o;
    o.x = l[p & 0xFF];
    o.y = l[(p >> 8) & 0xFF];
    o.z = l[(p >> 16) & 0xFF];
    o.w = l[(p >> 24) & 0xFF];
    ((float4*)out)[i] = o;
}

extern "C" void kernel_launch(void* const* d_in, const int* in_sizes, int n_in,
                              void* d_out, int out_size) {
    const float* sem = nullptr;
    const float* roi = nullptr;
    const float* bbx = nullptr;
    const int*   cls = nullptr;
    for (int i = 0; i < n_in; i++) {
        long long s = in_sizes[i];
        if (s >= 4000000)                 sem = (const float*)d_in[i];
        else if (s >= 100000)             roi = (const float*)d_in[i];
        else if (s >= 512 && s <= 4096)   bbx = (const float*)d_in[i];
        else if (s == 256) { if (!bbx) bbx = (const float*)d_in[i]; }
        else if (s <= 255)                cls = (const int*)d_in[i];
    }
    if (!sem) sem = (const float*)d_in[0];
    if (!roi) roi = (const float*)d_in[1];
    if (!bbx) bbx = (const float*)d_in[2];
    if (!cls) cls = (const int*)d_in[3];

    float* out = (float*)d_out;

    dim3 g1(H_, B_);
    k_main<<<g1, 192>>>(sem, roi, bbx, cls);
    k_post<<<1, 64>>>(cls, out, out_size);
    k_out<<<SEAM_TOT / 4 / 256, 256>>>(out);   // 1152 blocks
}

// round 13
// speedup vs baseline: 1.3534x; 1.3534x over previous
#include <cuda_runtime.h>
#include <math.h>

#define NS_   6
#define NT_   4
#define B_    2
#define N_    32
#define H_    768
#define W_    768
#define ROI_  28
#define C_    10           // NS + NT
#define L_    39           // 1 + NS + N
#define NEGV  (-100.0f)

#define SEAM_TOT (B_ * H_ * W_)                 // 1179648
#define FULL_OUT (SEAM_TOT + 2 * B_ * L_ + B_)  // 1179806
#define LUTN  (NS_ + N_)                        // 38
#define HW_   (H_ * W_)

// Scratch: zero-initialized at module load; k_post re-zeroes hist/cstuff after
// consuming them, so every graph replay starts clean (self-cleaning pipeline).
__device__ int g_hist[B_ * N_ * C_];
__device__ int g_cstuff[B_ * NS_];
__device__ __align__(16) unsigned char g_pp[B_ * H_ * W_];
__device__ float g_lutf[B_ * LUTN];

// XLA logistic_expander form: 1 / (1 + exp(-x)). sigmoid(-100) == 0 exactly.
__device__ __forceinline__ float jsig(float x) {
    return __fdiv_rn(1.0f, __fadd_rn(1.0f, expf(-x)));
}

// warp-aggregated shared-hist add: uniform fast path, match_any fallback
__device__ __forceinline__ void hist_add(int key, int lane,
                                         int* sh_hist, int* sh_cst) {
    const unsigned FULL = 0xffffffffu;
    int k0 = __shfl_sync(FULL, key, 0);
    if (__all_sync(FULL, key == k0)) {
        if (lane == 0) {
            if (k0 >= 64) atomicAdd(&sh_hist[k0 - 64], 32);
            else          atomicAdd(&sh_cst[k0], 32);
        }
    } else {
        unsigned mm = __match_any_sync(FULL, key);
        if (lane == __ffs(mm) - 1) {
            int cnt = __popc(mm);
            if (key >= 64) atomicAdd(&sh_hist[key - 64], cnt);
            else           atomicAdd(&sh_cst[key], cnt);
        }
    }
}

// ---- kernel 1: fused per-pixel argmax + histograms -------------------------
// TWO rows per block (single full wave: 768 blocks <= 888 resident at 6/SM).
// 256 thr x 3 px per row; both rows' stuff loads front-batched (12 scalar
// LDGs -> 2x MLP). Row-active instances for both rows built by two warps in
// one preamble. Per (warp,row,px-tile) ballot narrows to instances meeting
// the warp's 32-px window. Warp-uniform fast path skips thing channels.
// Tree argmax (first-max). Hybrid warp-aggregated histograms.
__global__ void __launch_bounds__(256, 6)
k_main(const float* __restrict__ sem, const float* __restrict__ roi,
       const float* __restrict__ bbx, const int* __restrict__ cls) {
    const unsigned FULL = 0xffffffffu;
    const int y0 = blockIdx.x * 2;
    const int b = blockIdx.y;
    const int t = threadIdx.x;
    const int lane = t & 31;

    __shared__ int sh_hist[N_ * C_];
    __shared__ int sh_cst[NS_];
    __shared__ int sh_K[2];
    __shared__ int sa_n[2][N_], sa_x0[2][N_], sa_x1r[2][N_];
    __shared__ int sa_xs[2][N_], sa_xe[2][N_];
    __shared__ int sa_inYm[2][N_], sa_cls[2][N_], sa_r0[2][N_], sa_r1[2][N_];
    __shared__ float sa_wy[2][N_], sa_rx[2][N_];

    for (int i = t; i < N_ * C_; i += 256) sh_hist[i] = 0;
    if (t < NS_) sh_cst[t] = 0;

    if (t < 64) {
        const int r = t >> 5;            // row 0 or 1 (one warp each)
        const int n = lane;              // instance index
        const int yy = y0 + r;
        const float* bb = bbx + (b * N_ + n) * 4;
        float y0f = bb[0], x0f = bb[1], y1f = bb[2], x1f = bb[3];
        int by0 = (int)floorf(y0f), bx0 = (int)floorf(x0f);
        int by1 = (int)floorf(y1f), bx1 = (int)floorf(x1f);
        int y1r = (int)(rintf(y1f) + 1.0f);   // round-half-even like jnp.round
        int x1r = (int)(rintf(x1f) + 1.0f);
        int hi = by1 - by0 + 1; if (hi < 1) hi = 1;
        int wi = bx1 - bx0 + 1; if (wi < 1) wi = 1;
        int ys = max(by0, 0), ye = min(by1 + 1, H_);
        float ry = __fdiv_rn(28.0f, (float)hi);
        float rx = __fdiv_rn(28.0f, (float)wi);
        int c = cls[b * N_ + n];
        int mskoff = ((b * N_ + n) * NT_ + c) * ROI_ * ROI_;

        bool inYs = (yy >= by0) && (yy < y1r);
        unsigned mask = __ballot_sync(FULL, inYs);
        if (lane == 0) sh_K[r] = __popc(mask);
        if (inYs) {
            int slot = __popc(mask & ((1u << lane) - 1u));
            sa_n[r][slot] = n;
            sa_x0[r][slot] = bx0; sa_x1r[r][slot] = x1r;
            sa_xs[r][slot] = max(bx0, 0); sa_xe[r][slot] = min(bx1 + 1, W_);
            sa_cls[r][slot] = c; sa_rx[r][slot] = rx;
            int inYm = (yy >= ys) && (yy < ye);
            sa_inYm[r][slot] = inYm;
            if (inYm) {
                float sy = __fsub_rn(
                    __fmul_rn(__fadd_rn(__fsub_rn((float)yy, (float)by0), 0.5f), ry),
                    0.5f);
                sy = fminf(fmaxf(sy, 0.0f), 27.0f);
                float fiy0 = floorf(sy);
                int iy0 = (int)fiy0;
                int iy1 = min(iy0 + 1, ROI_ - 1);
                sa_wy[r][slot] = __fsub_rn(sy, fiy0);
                sa_r0[r][slot] = mskoff + iy0 * ROI_;
                sa_r1[r][slot] = mskoff + iy1 * ROI_;
            } else {
                sa_wy[r][slot] = 0.0f; sa_r0[r][slot] = 0; sa_r1[r][slot] = 0;
            }
        }
    }
    __syncthreads();

    const float C_OUT = -0.0f;
    const float* semb0 = sem + (size_t)b * (C_ * HW_) + (size_t)y0 * W_;

    for (int px = 0; px < W_ / 256; px++) {
        const int x = t + px * 256;
        const int wlo = px * 256 + (t & ~31);

        // front-batched stuff loads for BOTH rows (12 independent LDGs)
        float sA[NS_], sB[NS_];
#pragma unroll
        for (int c = 0; c < NS_; c++) {
            sA[c] = __ldg(semb0 + (size_t)c * HW_ + x);
            sB[c] = __ldg(semb0 + (size_t)c * HW_ + W_ + x);
        }

#pragma unroll
        for (int r = 0; r < 2; r++) {
            const float* s = r ? sB : sA;
            const int y = y0 + r;
            const int K = sh_K[r];

            unsigned wmask;
            {
                bool inter = false;
                if (lane < K)
                    inter = (sa_x0[r][lane] <= wlo + 31) && (sa_x1r[r][lane] > wlo);
                wmask = __ballot_sync(FULL, inter);
            }

            // tree argmax over stuff (first-max: right wins on strict >)
            float s0 = s[0], s1 = s[1], s2 = s[2], s3 = s[3], s4 = s[4], s5 = s[5];
            int   i01 = (s1 > s0) ? 1 : 0;       float v01 = (s1 > s0) ? s1 : s0;
            int   i23 = (s3 > s2) ? 3 : 2;       float v23 = (s3 > s2) ? s3 : s2;
            int   i45 = (s5 > s4) ? 5 : 4;       float v45 = (s5 > s4) ? s5 : s4;
            int   i03 = (v23 > v01) ? i23 : i01; float v03 = (v23 > v01) ? v23 : v01;
            int   bi  = (v45 > v03) ? i45 : i03; float best = (v45 > v03) ? v45 : v03;

            bool slow = (wmask != 0) || __any_sync(FULL, best < 0.0f);
            if (!slow) {
                g_pp[((size_t)b * H_ + y) * W_ + x] = (unsigned char)bi;
                hist_add(bi, lane, sh_hist, sh_cst);
                continue;
            }

            // thing channels for this row
            float s6 = __ldg(semb0 + 6 * (size_t)HW_ + (size_t)r * W_ + x);
            float s7 = __ldg(semb0 + 7 * (size_t)HW_ + (size_t)r * W_ + x);
            float s8 = __ldg(semb0 + 8 * (size_t)HW_ + (size_t)r * W_ + x);
            float s9 = __ldg(semb0 + 9 * (size_t)HW_ + (size_t)r * W_ + x);
            int   i67 = (s7 > s6) ? 7 : 6;       float v67 = (s7 > s6) ? s7 : s6;
            int   i89 = (s9 > s8) ? 9 : 8;       float v89 = (s9 > s8) ? s9 : s8;
            int   i69 = (v89 > v67) ? i89 : i67; float v69 = (v89 > v67) ? v89 : v67;
            int   sem_pred = (v69 > best) ? i69 : bi;

            int nextn = 0;
            for (unsigned mrem = wmask; mrem; mrem &= mrem - 1) {
                int k = __ffs(mrem) - 1;
                int n = sa_n[r][k];
                if (n > nextn && best < 0.0f) { best = C_OUT; bi = NS_ + nextn; }
                nextn = n + 1;

                float v;
                bool sxin = (x >= sa_x0[r][k]) && (x < sa_x1r[r][k]);
                if (!sxin) {
                    v = C_OUT;
                } else {
                    int ck = sa_cls[r][k];
                    float a = (ck == 0) ? s6 : (ck == 1) ? s7 : (ck == 2) ? s8 : s9;
                    float m;
                    bool mxin = sa_inYm[r][k] && (x >= sa_xs[r][k]) && (x < sa_xe[r][k]);
                    if (mxin) {
                        float sx = __fsub_rn(
                            __fmul_rn(__fadd_rn(__fsub_rn((float)x, (float)sa_x0[r][k]), 0.5f),
                                      sa_rx[r][k]),
                            0.5f);
                        sx = fminf(fmaxf(sx, 0.0f), 27.0f);
                        float fix0 = floorf(sx);
                        int ix0 = (int)fix0;
                        int ix1 = min(ix0 + 1, ROI_ - 1);
                        float wx = __fsub_rn(sx, fix0);
                        const float* r0p = roi + sa_r0[r][k];
                        const float* r1p = roi + sa_r1[r][k];
                        float wy = sa_wy[r][k];
                        float omy = __fsub_rn(1.0f, wy);
                        float c0 = __fadd_rn(__fmul_rn(__ldg(r0p + ix0), omy),
                                             __fmul_rn(__ldg(r1p + ix0), wy));
                        float c1 = __fadd_rn(__fmul_rn(__ldg(r0p + ix1), omy),
                                             __fmul_rn(__ldg(r1p + ix1), wy));
                        float omx = __fsub_rn(1.0f, wx);
                        m = __fadd_rn(__fmul_rn(c0, omx), __fmul_rn(c1, wx));
                    } else {
                        m = NEGV;
                    }
                    v = __fmul_rn(__fadd_rn(jsig(a), jsig(m)), __fadd_rn(a, m));
                }
                if (v > best) { best = v; bi = NS_ + n; }
            }
            if (nextn < N_ && best < 0.0f) { best = C_OUT; bi = NS_ + nextn; }

            g_pp[((size_t)b * H_ + y) * W_ + x] = (unsigned char)bi;

            int key = (bi >= NS_) ? (64 + (bi - NS_) * C_ + sem_pred) : bi;
            hist_add(key, lane, sh_hist, sh_cst);
        }
    }
    __syncthreads();

    for (int i = t; i < N_ * C_; i += 256) {
        int v = sh_hist[i];
        if (v) atomicAdd(&g_hist[b * N_ * C_ + i], v);
    }
    if (t < NS_) {
        int v = sh_cst[t];
        if (v) atomicAdd(&g_cstuff[b * NS_ + t], v);
    }
}

// ---- kernel 2: warp-parallel relabel + small outputs; self-cleans scratch --
__global__ void __launch_bounds__(64)
k_post(const int* __restrict__ cls, float* __restrict__ out, int out_size) {
    const unsigned FULL = 0xffffffffu;
    int b = threadIdx.x >> 5;
    int lane = threadIdx.x & 31;
    int* hist = g_hist + (b * N_ + lane) * C_;

    int tot = 0, mc = 0, smax = 0;
#pragma unroll
    for (int c = 0; c < C_; c++) {
        int h = hist[c];
        tot += h;
        if (h > mc) { mc = h; smax = c; }
    }
    int pres = (tot > 0);
    int tmp = cls[b * N_ + lane] + NS_;
    int br1 = (smax == tmp);
    int br2 = (!br1) && (2 * mc >= tot) && (smax < NS_) && pres;
    int semlab = br2 ? smax : tmp;
    int kept = pres && !br2;

    int sp[NS_];
#pragma unroll
    for (int c = 0; c < NS_; c++) {
        int v = (semlab == c) ? tot : 0;
#pragma unroll
        for (int off = 16; off; off >>= 1) v += __shfl_down_sync(FULL, v, off);
        v = __shfl_sync(FULL, v, 0);
        sp[c] = g_cstuff[b * NS_ + c] + v;
    }

    int srank[NS_], nst = 0;
#pragma unroll
    for (int c = 0; c < NS_; c++) { if (sp[c] > 0) nst++; srank[c] = nst - 1; }

    unsigned kb = __ballot_sync(FULL, kept);
    int rank_k = __popc(kb & ((1u << lane) - 1u));
    int rk = __popc(kb);

    float* lut = g_lutf + b * LUTN;
    if (lane < NS_) lut[lane] = (float)(srank[lane] + 1);
    int lv = kept ? (1 + nst + rank_k)
                  : ((semlab < NS_) ? (srank[semlab] + 1) : 0);
    lut[NS_ + lane] = (float)lv;

    if (out_size >= FULL_OUT) {
        float* pcls = out + SEAM_TOT + b * L_;
        float* pisc = out + SEAM_TOT + B_ * L_ + b * L_;
        pcls[lane] = -1.0f;
        if (lane < L_ - 32) pcls[32 + lane] = -1.0f;
        __syncwarp(FULL);
        if (lane == 0) pcls[0] = 255.0f;
        if (lane < NS_ && sp[lane] > 0) pcls[1 + srank[lane]] = (float)lane;
        if (kept) pcls[1 + nst + rank_k] = (float)tmp;
        int vl = 1 + nst + rk;
        pisc[lane] = (lane < vl) ? 0.0f : -1.0f;
        if (lane < L_ - 32) pisc[32 + lane] = ((32 + lane) < vl) ? 0.0f : -1.0f;
        if (lane == 0) out[SEAM_TOT + 2 * B_ * L_ + b] = (float)vl;
    }
    // zero any residual output beyond the defined region (usually empty loop)
    for (int i = FULL_OUT + threadIdx.x; i < out_size; i += 64) out[i] = 0.0f;

    // self-clean scratch for the next graph replay
#pragma unroll
    for (int c = 0; c < C_; c++) hist[c] = 0;
    if (lane < NS_) g_cstuff[b * NS_ + lane] = 0;
}

// ---- kernel 3: LUT remap; shared LUT, 1 quad/thread, 1152 blocks -----------
__global__ void __launch_bounds__(256)
k_out(float* __restrict__ out) {
    __shared__ float lut[B_ * LUTN];
    int t = threadIdx.x;
    if (t < B_ * LUTN) lut[t] = g_lutf[t];
    __syncthreads();
    int i = blockIdx.x * 256 + t;              // quad index
    const int HWQ = HW_ / 4;
    unsigned int p = ((const unsigned int*)g_pp)[i];
    const float* l = lut + ((i >= HWQ) ? LUTN : 0);
    float4 o;
    o.x = l[p & 0xFF];
    o.y = l[(p >> 8) & 0xFF];
    o.z = l[(p >> 16) & 0xFF];
    o.w = l[(p >> 24) & 0xFF];
    ((float4*)out)[i] = o;
}

extern "C" void kernel_launch(void* const* d_in, const int* in_sizes, int n_in,
                              void* d_out, int out_size) {
    const float* sem = nullptr;
    const float* roi = nullptr;
    const float* bbx = nullptr;
    const int*   cls = nullptr;
    for (int i = 0; i < n_in; i++) {
        long long s = in_sizes[i];
        if (s >= 4000000)                 sem = (const float*)d_in[i];
        else if (s >= 100000)             roi = (const float*)d_in[i];
        else if (s >= 512 && s <= 4096)   bbx = (const float*)d_in[i];
        else if (s == 256) { if (!bbx) bbx = (const float*)d_in[i]; }
        else if (s <= 255)                cls = (const int*)d_in[i];
    }
    if (!sem) sem = (const float*)d_in[0];
    if (!roi) roi = (const float*)d_in[1];
    if (!bbx) bbx = (const float*)d_in[2];
    if (!cls) cls = (const int*)d_in[3];

    float* out = (float*)d_out;

    dim3 g1(H_ / 2, B_);                       // 384 x 2 = 768 blocks: 1 wave
    k_main<<<g1, 256>>>(sem, roi, bbx, cls);
    k_post<<<1, 64>>>(cls, out, out_size);
    k_out<<<SEAM_TOT / 4 / 256, 256>>>(out);   // 1152 blocks
}

// round 14
// speedup vs baseline: 1.4494x; 1.0709x over previous
#include <cuda_runtime.h>
#include <math.h>

#define NS_   6
#define NT_   4
#define B_    2
#define N_    32
#define H_    768
#define W_    768
#define ROI_  28
#define C_    10           // NS + NT
#define L_    39           // 1 + NS + N
#define NEGV  (-100.0f)

#define SEAM_TOT (B_ * H_ * W_)                 // 1179648
#define FULL_OUT (SEAM_TOT + 2 * B_ * L_ + B_)  // 1179806
#define LUTN  (NS_ + N_)                        // 38
#define HW_   (H_ * W_)

// Scratch: zero-initialized at module load; k_post re-zeroes hist/cstuff after
// consuming them, so every graph replay starts clean (self-cleaning pipeline).
__device__ int g_hist[B_ * N_ * C_];
__device__ int g_cstuff[B_ * NS_];
__device__ __align__(16) unsigned char g_pp[B_ * H_ * W_];
__device__ float g_lutf[B_ * LUTN];

// XLA logistic_expander form: 1 / (1 + exp(-x)). sigmoid(-100) == 0 exactly.
__device__ __forceinline__ float jsig(float x) {
    return __fdiv_rn(1.0f, __fadd_rn(1.0f, expf(-x)));
}

// warp-aggregated shared-hist add: uniform fast path, match_any fallback
__device__ __forceinline__ void hist_add(int key, int lane,
                                         int* sh_hist, int* sh_cst) {
    const unsigned FULL = 0xffffffffu;
    int k0 = __shfl_sync(FULL, key, 0);
    if (__all_sync(FULL, key == k0)) {
        if (lane == 0) {
            if (k0 >= 64) atomicAdd(&sh_hist[k0 - 64], 32);
            else          atomicAdd(&sh_cst[k0], 32);
        }
    } else {
        unsigned mm = __match_any_sync(FULL, key);
        if (lane == __ffs(mm) - 1) {
            int cnt = __popc(mm);
            if (key >= 64) atomicAdd(&sh_hist[key - 64], cnt);
            else           atomicAdd(&sh_cst[key], cnt);
        }
    }
}

// ---- kernel 1: fused per-pixel argmax + histograms -------------------------
// One block per (row, batch); 256 thr x 3 px; 7 blocks/SM forced (36 regs)
// for occupancy. Row-active instances compacted; per (warp, 256-px tile)
// ballot narrows to instances meeting the warp's 32-px window. Warp-uniform
// fast path skips thing channels. Tree argmax (first-max semantics). Hybrid
// warp-aggregated histograms.
__global__ void __launch_bounds__(256, 7)
k_main(const float* __restrict__ sem, const float* __restrict__ roi,
       const float* __restrict__ bbx, const int* __restrict__ cls) {
    const unsigned FULL = 0xffffffffu;
    const int y = blockIdx.x;
    const int b = blockIdx.y;
    const int t = threadIdx.x;
    const int lane = t & 31;

    __shared__ int sh_hist[N_ * C_];
    __shared__ int sh_cst[NS_];
    __shared__ int sh_K;
    __shared__ int sa_n[N_], sa_x0[N_], sa_x1r[N_], sa_xs[N_], sa_xe[N_];
    __shared__ int sa_inYm[N_], sa_cls[N_], sa_r0[N_], sa_r1[N_];
    __shared__ float sa_wy[N_], sa_rx[N_];

    for (int i = t; i < N_ * C_; i += 256) sh_hist[i] = 0;
    if (t < NS_) sh_cst[t] = 0;

    if (t < 32) {
        const float* bb = bbx + (b * N_ + t) * 4;
        float y0f = bb[0], x0f = bb[1], y1f = bb[2], x1f = bb[3];
        int y0 = (int)floorf(y0f), x0 = (int)floorf(x0f);
        int y1 = (int)floorf(y1f), x1 = (int)floorf(x1f);
        int y1r = (int)(rintf(y1f) + 1.0f);   // round-half-even like jnp.round
        int x1r = (int)(rintf(x1f) + 1.0f);
        int hi = y1 - y0 + 1; if (hi < 1) hi = 1;
        int wi = x1 - x0 + 1; if (wi < 1) wi = 1;
        int ys = max(y0, 0), ye = min(y1 + 1, H_);
        float ry = __fdiv_rn(28.0f, (float)hi);
        float rx = __fdiv_rn(28.0f, (float)wi);
        int c = cls[b * N_ + t];
        int mskoff = ((b * N_ + t) * NT_ + c) * ROI_ * ROI_;

        bool inYs = (y >= y0) && (y < y1r);
        unsigned mask = __ballot_sync(FULL, inYs);
        if (t == 0) sh_K = __popc(mask);
        if (inYs) {
            int slot = __popc(mask & ((1u << t) - 1u));
            sa_n[slot] = t;
            sa_x0[slot] = x0; sa_x1r[slot] = x1r;
            sa_xs[slot] = max(x0, 0); sa_xe[slot] = min(x1 + 1, W_);
            sa_cls[slot] = c; sa_rx[slot] = rx;
            int inYm = (y >= ys) && (y < ye);
            sa_inYm[slot] = inYm;
            if (inYm) {
                float sy = __fsub_rn(
                    __fmul_rn(__fadd_rn(__fsub_rn((float)y, (float)y0), 0.5f), ry),
                    0.5f);
                sy = fminf(fmaxf(sy, 0.0f), 27.0f);
                float fiy0 = floorf(sy);
                int iy0 = (int)fiy0;
                int iy1 = min(iy0 + 1, ROI_ - 1);
                sa_wy[slot] = __fsub_rn(sy, fiy0);
                sa_r0[slot] = mskoff + iy0 * ROI_;
                sa_r1[slot] = mskoff + iy1 * ROI_;
            } else {
                sa_wy[slot] = 0.0f; sa_r0[slot] = 0; sa_r1[slot] = 0;
            }
        }
    }
    __syncthreads();

    const int K = sh_K;
    const float C_OUT = -0.0f;
    const float* semb0 = sem + (size_t)b * (C_ * HW_) + (size_t)y * W_;

    for (int px = 0; px < W_ / 256; px++) {
        const int x = t + px * 256;

        // warp filter: instances whose strict x-interval meets this warp's
        // 32-pixel window
        unsigned wmask;
        {
            int wlo = px * 256 + (t & ~31);
            bool inter = false;
            if (lane < K) inter = (sa_x0[lane] <= wlo + 31) && (sa_x1r[lane] > wlo);
            wmask = __ballot_sync(FULL, inter);
        }

        // stuff channels (0..5) + tree argmax (first-max semantics)
        float s0 = __ldg(semb0 + 0 * (size_t)HW_ + x);
        float s1 = __ldg(semb0 + 1 * (size_t)HW_ + x);
        float s2 = __ldg(semb0 + 2 * (size_t)HW_ + x);
        float s3 = __ldg(semb0 + 3 * (size_t)HW_ + x);
        float s4 = __ldg(semb0 + 4 * (size_t)HW_ + x);
        float s5 = __ldg(semb0 + 5 * (size_t)HW_ + x);
        int   i01 = (s1 > s0) ? 1 : 0;       float v01 = (s1 > s0) ? s1 : s0;
        int   i23 = (s3 > s2) ? 3 : 2;       float v23 = (s3 > s2) ? s3 : s2;
        int   i45 = (s5 > s4) ? 5 : 4;       float v45 = (s5 > s4) ? s5 : s4;
        int   i03 = (v23 > v01) ? i23 : i01; float v03 = (v23 > v01) ? v23 : v01;
        int   bi  = (v45 > v03) ? i45 : i03; float best = (v45 > v03) ? v45 : v03;

        // FAST PATH: no instance window here and C_OUT can't win anywhere
        bool slow = (wmask != 0) || __any_sync(FULL, best < 0.0f);
        if (!slow) {
            g_pp[((size_t)b * H_ + y) * W_ + x] = (unsigned char)bi;
            hist_add(bi, lane, sh_hist, sh_cst);
            continue;
        }

        // thing channels (6..9) + sem argmax extension
        float s6 = __ldg(semb0 + 6 * (size_t)HW_ + x);
        float s7 = __ldg(semb0 + 7 * (size_t)HW_ + x);
        float s8 = __ldg(semb0 + 8 * (size_t)HW_ + x);
        float s9 = __ldg(semb0 + 9 * (size_t)HW_ + x);
        int   i67 = (s7 > s6) ? 7 : 6;       float v67 = (s7 > s6) ? s7 : s6;
        int   i89 = (s9 > s8) ? 9 : 8;       float v89 = (s9 > s8) ? s9 : s8;
        int   i69 = (v89 > v67) ? i89 : i67; float v69 = (v89 > v67) ? v89 : v67;
        int   sem_pred = (v69 > best) ? i69 : bi;

        int nextn = 0;
        for (unsigned mrem = wmask; mrem; mrem &= mrem - 1) {
            int k = __ffs(mrem) - 1;
            int n = sa_n[k];
            if (n > nextn && best < 0.0f) { best = C_OUT; bi = NS_ + nextn; }
            nextn = n + 1;

            float v;
            bool sxin = (x >= sa_x0[k]) && (x < sa_x1r[k]);
            if (!sxin) {
                v = C_OUT;
            } else {
                int ck = sa_cls[k];
                float a = (ck == 0) ? s6 : (ck == 1) ? s7 : (ck == 2) ? s8 : s9;
                float m;
                bool mxin = sa_inYm[k] && (x >= sa_xs[k]) && (x < sa_xe[k]);
                if (mxin) {
                    float sx = __fsub_rn(
                        __fmul_rn(__fadd_rn(__fsub_rn((float)x, (float)sa_x0[k]), 0.5f),
                                  sa_rx[k]),
                        0.5f);
                    sx = fminf(fmaxf(sx, 0.0f), 27.0f);
                    float fix0 = floorf(sx);
                    int ix0 = (int)fix0;
                    int ix1 = min(ix0 + 1, ROI_ - 1);
                    float wx = __fsub_rn(sx, fix0);
                    const float* r0 = roi + sa_r0[k];
                    const float* r1 = roi + sa_r1[k];
                    float wy = sa_wy[k];
                    float omy = __fsub_rn(1.0f, wy);
                    float c0 = __fadd_rn(__fmul_rn(__ldg(r0 + ix0), omy),
                                         __fmul_rn(__ldg(r1 + ix0), wy));
                    float c1 = __fadd_rn(__fmul_rn(__ldg(r0 + ix1), omy),
                                         __fmul_rn(__ldg(r1 + ix1), wy));
                    float omx = __fsub_rn(1.0f, wx);
                    m = __fadd_rn(__fmul_rn(c0, omx), __fmul_rn(c1, wx));
                } else {
                    m = NEGV;
                }
                v = __fmul_rn(__fadd_rn(jsig(a), jsig(m)), __fadd_rn(a, m));
            }
            if (v > best) { best = v; bi = NS_ + n; }
        }
        if (nextn < N_ && best < 0.0f) { best = C_OUT; bi = NS_ + nextn; }

        g_pp[((size_t)b * H_ + y) * W_ + x] = (unsigned char)bi;

        int key = (bi >= NS_) ? (64 + (bi - NS_) * C_ + sem_pred) : bi;
        hist_add(key, lane, sh_hist, sh_cst);
    }
    __syncthreads();

    for (int i = t; i < N_ * C_; i += 256) {
        int v = sh_hist[i];
        if (v) atomicAdd(&g_hist[b * N_ * C_ + i], v);
    }
    if (t < NS_) {
        int v = sh_cst[t];
        if (v) atomicAdd(&g_cstuff[b * NS_ + t], v);
    }
}

// ---- kernel 2: warp-parallel relabel + small outputs; self-cleans scratch --
__global__ void __launch_bounds__(64)
k_post(const int* __restrict__ cls, float* __restrict__ out, int out_size) {
    const unsigned FULL = 0xffffffffu;
    int b = threadIdx.x >> 5;
    int lane = threadIdx.x & 31;
    int* hist = g_hist + (b * N_ + lane) * C_;

    int tot = 0, mc = 0, smax = 0;
#pragma unroll
    for (int c = 0; c < C_; c++) {
        int h = hist[c];
        tot += h;
        if (h > mc) { mc = h; smax = c; }
    }
    int pres = (tot > 0);
    int tmp = cls[b * N_ + lane] + NS_;
    int br1 = (smax == tmp);
    int br2 = (!br1) && (2 * mc >= tot) && (smax < NS_) && pres;
    int semlab = br2 ? smax : tmp;
    int kept = pres && !br2;

    int sp[NS_];
#pragma unroll
    for (int c = 0; c < NS_; c++) {
        int v = (semlab == c) ? tot : 0;
#pragma unroll
        for (int off = 16; off; off >>= 1) v += __shfl_down_sync(FULL, v, off);
        v = __shfl_sync(FULL, v, 0);
        sp[c] = g_cstuff[b * NS_ + c] + v;
    }

    int srank[NS_], nst = 0;
#pragma unroll
    for (int c = 0; c < NS_; c++) { if (sp[c] > 0) nst++; srank[c] = nst - 1; }

    unsigned kb = __ballot_sync(FULL, kept);
    int rank_k = __popc(kb & ((1u << lane) - 1u));
    int rk = __popc(kb);

    float* lut = g_lutf + b * LUTN;
    if (lane < NS_) lut[lane] = (float)(srank[lane] + 1);
    int lv = kept ? (1 + nst + rank_k)
                  : ((semlab < NS_) ? (srank[semlab] + 1) : 0);
    lut[NS_ + lane] = (float)lv;

    if (out_size >= FULL_OUT) {
        float* pcls = out + SEAM_TOT + b * L_;
        float* pisc = out + SEAM_TOT + B_ * L_ + b * L_;
        pcls[lane] = -1.0f;
        if (lane < L_ - 32) pcls[32 + lane] = -1.0f;
        __syncwarp(FULL);
        if (lane == 0) pcls[0] = 255.0f;
        if (lane < NS_ && sp[lane] > 0) pcls[1 + srank[lane]] = (float)lane;
        if (kept) pcls[1 + nst + rank_k] = (float)tmp;
        int vl = 1 + nst + rk;
        pisc[lane] = (lane < vl) ? 0.0f : -1.0f;
        if (lane < L_ - 32) pisc[32 + lane] = ((32 + lane) < vl) ? 0.0f : -1.0f;
        if (lane == 0) out[SEAM_TOT + 2 * B_ * L_ + b] = (float)vl;
    }
    // zero any residual output beyond the defined region (usually empty loop)
    for (int i = FULL_OUT + threadIdx.x; i < out_size; i += 64) out[i] = 0.0f;

    // self-clean scratch for the next graph replay
#pragma unroll
    for (int c = 0; c < C_; c++) hist[c] = 0;
    if (lane < NS_) g_cstuff[b * NS_ + lane] = 0;
}

// ---- kernel 3: LUT remap; shared LUT, 1 quad/thread, 1152 blocks -----------
__global__ void __launch_bounds__(256)
k_out(float* __restrict__ out) {
    __shared__ float lut[B_ * LUTN];
    int t = threadIdx.x;
    if (t < B_ * LUTN) lut[t] = g_lutf[t];
    __syncthreads();
    int i = blockIdx.x * 256 + t;              // quad index
    const int HWQ = HW_ / 4;
    unsigned int p = ((const unsigned int*)g_pp)[i];
    const float* l = lut + ((i >= HWQ) ? LUTN : 0);
    float4 o;
    o.x = l[p & 0xFF];
    o.y = l[(p >> 8) & 0xFF];
    o.z = l[(p >> 16) & 0xFF];
    o.w = l[(p >> 24) & 0xFF];
    ((float4*)out)[i] = o;
}

extern "C" void kernel_launch(void* const* d_in, const int* in_sizes, int n_in,
                              void* d_out, int out_size) {
    const float* sem = nullptr;
    const float* roi = nullptr;
    const float* bbx = nullptr;
    const int*   cls = nullptr;
    for (int i = 0; i < n_in; i++) {
        long long s = in_sizes[i];
        if (s >= 4000000)                 sem = (const float*)d_in[i];
        else if (s >= 100000)             roi = (const float*)d_in[i];
        else if (s >= 512 && s <= 4096)   bbx = (const float*)d_in[i];
        else if (s == 256) { if (!bbx) bbx = (const float*)d_in[i]; }
        else if (s <= 255)                cls = (const int*)d_in[i];
    }
    if (!sem) sem = (const float*)d_in[0];
    if (!roi) roi = (const float*)d_in[1];
    if (!bbx) bbx = (const float*)d_in[2];
    if (!cls) cls = (const int*)d_in[3];

    float* out = (float*)d_out;

    dim3 g1(H_, B_);
    k_main<<<g1, 256>>>(sem, roi, bbx, cls);
    k_post<<<1, 64>>>(cls, out, out_size);
    k_out<<<SEAM_TOT / 4 / 256, 256>>>(out);   // 1152 blocks
}

// round 15
// speedup vs baseline: 1.5903x; 1.0972x over previous
#include <cuda_runtime.h>
#include <math.h>

#define NS_   6
#define NT_   4
#define B_    2
#define N_    32
#define H_    768
#define W_    768
#define ROI_  28
#define C_    10           // NS + NT
#define L_    39           // 1 + NS + N
#define NEGV  (-100.0f)

#define SEAM_TOT (B_ * H_ * W_)                 // 1179648
#define FULL_OUT (SEAM_TOT + 2 * B_ * L_ + B_)  // 1179806
#define LUTN  (NS_ + N_)                        // 38
#define HW_   (H_ * W_)

// Scratch: zero-initialized at module load; k_post re-zeroes hist/cstuff after
// consuming them, so every graph replay starts clean (self-cleaning pipeline).
__device__ int g_hist[B_ * N_ * C_];
__device__ int g_cstuff[B_ * NS_];
__device__ __align__(16) unsigned char g_pp[B_ * H_ * W_];
__device__ float g_lutf[B_ * LUTN];

// XLA logistic_expander form: 1 / (1 + exp(-x)). sigmoid(-100) == 0 exactly.
__device__ __forceinline__ float jsig(float x) {
    return __fdiv_rn(1.0f, __fadd_rn(1.0f, expf(-x)));
}

// warp-aggregated shared-hist add: uniform fast path, match_any fallback
__device__ __forceinline__ void hist_add(int key, int lane,
                                         int* sh_hist, int* sh_cst) {
    const unsigned FULL = 0xffffffffu;
    int k0 = __shfl_sync(FULL, key, 0);
    if (__all_sync(FULL, key == k0)) {
        if (lane == 0) {
            if (k0 >= 64) atomicAdd(&sh_hist[k0 - 64], 32);
            else          atomicAdd(&sh_cst[k0], 32);
        }
    } else {
        unsigned mm = __match_any_sync(FULL, key);
        if (lane == __ffs(mm) - 1) {
            int cnt = __popc(mm);
            if (key >= 64) atomicAdd(&sh_hist[key - 64], cnt);
            else           atomicAdd(&sh_cst[key], cnt);
        }
    }
}

// ---- kernel 1: fused per-pixel argmax + histograms -------------------------
// One block per (row, batch); 256 thr x 3 px; 7 blocks/SM. Row-active
// instances compacted (t<32), then the y-interpolated 28-float mask row
// m_y = m0*(1-wy) + m1*wy is PRECOMPUTED into shared memory per active
// instance (exact reference op order). The per-pixel bilinear reduces to two
// LDS + x-interp — cutting the slow-path dependency chain from ~400 to ~150
// cycles. Per-warp 32-px-window ballot filter; warp-uniform fast path skips
// thing channels; tree argmax (first-max); hybrid warp-aggregated histograms.
__global__ void __launch_bounds__(256, 7)
k_main(const float* __restrict__ sem, const float* __restrict__ roi,
       const float* __restrict__ bbx, const int* __restrict__ cls) {
    const unsigned FULL = 0xffffffffu;
    const int y = blockIdx.x;
    const int b = blockIdx.y;
    const int t = threadIdx.x;
    const int lane = t & 31;

    __shared__ int sh_hist[N_ * C_];
    __shared__ int sh_cst[NS_];
    __shared__ int sh_K;
    __shared__ int sa_n[N_], sa_x0[N_], sa_x1r[N_], sa_xs[N_], sa_xe[N_];
    __shared__ int sa_inYm[N_], sa_cls[N_], sa_r0[N_], sa_r1[N_];
    __shared__ float sa_wy[N_], sa_rx[N_];
    __shared__ float sh_my[N_][ROI_];       // y-interpolated mask rows

    for (int i = t; i < N_ * C_; i += 256) sh_hist[i] = 0;
    if (t < NS_) sh_cst[t] = 0;

    if (t < 32) {
        const float* bb = bbx + (b * N_ + t) * 4;
        float y0f = bb[0], x0f = bb[1], y1f = bb[2], x1f = bb[3];
        int y0 = (int)floorf(y0f), x0 = (int)floorf(x0f);
        int y1 = (int)floorf(y1f), x1 = (int)floorf(x1f);
        int y1r = (int)(rintf(y1f) + 1.0f);   // round-half-even like jnp.round
        int x1r = (int)(rintf(x1f) + 1.0f);
        int hi = y1 - y0 + 1; if (hi < 1) hi = 1;
        int wi = x1 - x0 + 1; if (wi < 1) wi = 1;
        int ys = max(y0, 0), ye = min(y1 + 1, H_);
        float ry = __fdiv_rn(28.0f, (float)hi);
        float rx = __fdiv_rn(28.0f, (float)wi);
        int c = cls[b * N_ + t];
        int mskoff = ((b * N_ + t) * NT_ + c) * ROI_ * ROI_;

        bool inYs = (y >= y0) && (y < y1r);
        unsigned mask = __ballot_sync(FULL, inYs);
        if (t == 0) sh_K = __popc(mask);
        if (inYs) {
            int slot = __popc(mask & ((1u << t) - 1u));
            sa_n[slot] = t;
            sa_x0[slot] = x0; sa_x1r[slot] = x1r;
            sa_xs[slot] = max(x0, 0); sa_xe[slot] = min(x1 + 1, W_);
            sa_cls[slot] = c; sa_rx[slot] = rx;
            int inYm = (y >= ys) && (y < ye);
            sa_inYm[slot] = inYm;
            if (inYm) {
                float sy = __fsub_rn(
                    __fmul_rn(__fadd_rn(__fsub_rn((float)y, (float)y0), 0.5f), ry),
                    0.5f);
                sy = fminf(fmaxf(sy, 0.0f), 27.0f);
                float fiy0 = floorf(sy);
                int iy0 = (int)fiy0;
                int iy1 = min(iy0 + 1, ROI_ - 1);
                sa_wy[slot] = __fsub_rn(sy, fiy0);
                sa_r0[slot] = mskoff + iy0 * ROI_;
                sa_r1[slot] = mskoff + iy1 * ROI_;
            } else {
                sa_wy[slot] = 0.0f; sa_r0[slot] = 0; sa_r1[slot] = 0;
            }
        }
    }
    __syncthreads();

    const int K = sh_K;

    // precompute y-interpolated mask rows (exact ref order: m0*(1-wy)+m1*wy)
    for (int idx = t; idx < K * ROI_; idx += 256) {
        int slot = idx / ROI_, col = idx - slot * ROI_;
        if (sa_inYm[slot]) {
            float m0 = __ldg(roi + sa_r0[slot] + col);
            float m1 = __ldg(roi + sa_r1[slot] + col);
            float wy = sa_wy[slot];
            sh_my[slot][col] = __fadd_rn(__fmul_rn(m0, __fsub_rn(1.0f, wy)),
                                         __fmul_rn(m1, wy));
        }
    }
    __syncthreads();

    const float C_OUT = -0.0f;
    const float* semb0 = sem + (size_t)b * (C_ * HW_) + (size_t)y * W_;

    for (int px = 0; px < W_ / 256; px++) {
        const int x = t + px * 256;

        // warp filter: instances whose strict x-interval meets this warp's
        // 32-pixel window
        unsigned wmask;
        {
            int wlo = px * 256 + (t & ~31);
            bool inter = false;
            if (lane < K) inter = (sa_x0[lane] <= wlo + 31) && (sa_x1r[lane] > wlo);
            wmask = __ballot_sync(FULL, inter);
        }

        // stuff channels (0..5) + tree argmax (first-max semantics)
        float s0 = __ldg(semb0 + 0 * (size_t)HW_ + x);
        float s1 = __ldg(semb0 + 1 * (size_t)HW_ + x);
        float s2 = __ldg(semb0 + 2 * (size_t)HW_ + x);
        float s3 = __ldg(semb0 + 3 * (size_t)HW_ + x);
        float s4 = __ldg(semb0 + 4 * (size_t)HW_ + x);
        float s5 = __ldg(semb0 + 5 * (size_t)HW_ + x);
        int   i01 = (s1 > s0) ? 1 : 0;       float v01 = (s1 > s0) ? s1 : s0;
        int   i23 = (s3 > s2) ? 3 : 2;       float v23 = (s3 > s2) ? s3 : s2;
        int   i45 = (s5 > s4) ? 5 : 4;       float v45 = (s5 > s4) ? s5 : s4;
        int   i03 = (v23 > v01) ? i23 : i01; float v03 = (v23 > v01) ? v23 : v01;
        int   bi  = (v45 > v03) ? i45 : i03; float best = (v45 > v03) ? v45 : v03;

        // FAST PATH: no instance window here and C_OUT can't win anywhere
        bool slow = (wmask != 0) || __any_sync(FULL, best < 0.0f);
        if (!slow) {
            g_pp[((size_t)b * H_ + y) * W_ + x] = (unsigned char)bi;
            hist_add(bi, lane, sh_hist, sh_cst);
            continue;
        }

        // thing channels (6..9) + sem argmax extension
        float s6 = __ldg(semb0 + 6 * (size_t)HW_ + x);
        float s7 = __ldg(semb0 + 7 * (size_t)HW_ + x);
        float s8 = __ldg(semb0 + 8 * (size_t)HW_ + x);
        float s9 = __ldg(semb0 + 9 * (size_t)HW_ + x);
        int   i67 = (s7 > s6) ? 7 : 6;       float v67 = (s7 > s6) ? s7 : s6;
        int   i89 = (s9 > s8) ? 9 : 8;       float v89 = (s9 > s8) ? s9 : s8;
        int   i69 = (v89 > v67) ? i89 : i67; float v69 = (v89 > v67) ? v89 : v67;
        int   sem_pred = (v69 > best) ? i69 : bi;

        int nextn = 0;
        for (unsigned mrem = wmask; mrem; mrem &= mrem - 1) {
            int k = __ffs(mrem) - 1;
            int n = sa_n[k];
            if (n > nextn && best < 0.0f) { best = C_OUT; bi = NS_ + nextn; }
            nextn = n + 1;

            float v;
            bool sxin = (x >= sa_x0[k]) && (x < sa_x1r[k]);
            if (!sxin) {
                v = C_OUT;
            } else {
                int ck = sa_cls[k];
                float a = (ck == 0) ? s6 : (ck == 1) ? s7 : (ck == 2) ? s8 : s9;
                float m;
                bool mxin = sa_inYm[k] && (x >= sa_xs[k]) && (x < sa_xe[k]);
                if (mxin) {
                    float sx = __fsub_rn(
                        __fmul_rn(__fadd_rn(__fsub_rn((float)x, (float)sa_x0[k]), 0.5f),
                                  sa_rx[k]),
                        0.5f);
                    sx = fminf(fmaxf(sx, 0.0f), 27.0f);
                    float fix0 = floorf(sx);
                    int ix0 = (int)fix0;
                    int ix1 = min(ix0 + 1, ROI_ - 1);
                    float wx = __fsub_rn(sx, fix0);
                    float c0 = sh_my[k][ix0];
                    float c1 = sh_my[k][ix1];
                    float omx = __fsub_rn(1.0f, wx);
                    m = __fadd_rn(__fmul_rn(c0, omx), __fmul_rn(c1, wx));
                } else {
                    m = NEGV;
                }
                v = __fmul_rn(__fadd_rn(jsig(a), jsig(m)), __fadd_rn(a, m));
            }
            if (v > best) { best = v; bi = NS_ + n; }
        }
        if (nextn < N_ && best < 0.0f) { best = C_OUT; bi = NS_ + nextn; }

        g_pp[((size_t)b * H_ + y) * W_ + x] = (unsigned char)bi;

        int key = (bi >= NS_) ? (64 + (bi - NS_) * C_ + sem_pred) : bi;
        hist_add(key, lane, sh_hist, sh_cst);
    }
    __syncthreads();

    for (int i = t; i < N_ * C_; i += 256) {
        int v = sh_hist[i];
        if (v) atomicAdd(&g_hist[b * N_ * C_ + i], v);
    }
    if (t < NS_) {
        int v = sh_cst[t];
        if (v) atomicAdd(&g_cstuff[b * NS_ + t], v);
    }
}

// ---- kernel 2: warp-parallel relabel + small outputs; self-cleans scratch --
__global__ void __launch_bounds__(64)
k_post(const int* __restrict__ cls, float* __restrict__ out, int out_size) {
    const unsigned FULL = 0xffffffffu;
    int b = threadIdx.x >> 5;
    int lane = threadIdx.x & 31;
    int* hist = g_hist + (b * N_ + lane) * C_;

    int tot = 0, mc = 0, smax = 0;
#pragma unroll
    for (int c = 0; c < C_; c++) {
        int h = hist[c];
        tot += h;
        if (h > mc) { mc = h; smax = c; }
    }
    int pres = (tot > 0);
    int tmp = cls[b * N_ + lane] + NS_;
    int br1 = (smax == tmp);
    int br2 = (!br1) && (2 * mc >= tot) && (smax < NS_) && pres;
    int semlab = br2 ? smax : tmp;
    int kept = pres && !br2;

    int sp[NS_];
#pragma unroll
    for (int c = 0; c < NS_; c++) {
        int v = (semlab == c) ? tot : 0;
#pragma unroll
        for (int off = 16; off; off >>= 1) v += __shfl_down_sync(FULL, v, off);
        v = __shfl_sync(FULL, v, 0);
        sp[c] = g_cstuff[b * NS_ + c] + v;
    }

    int srank[NS_], nst = 0;
#pragma unroll
    for (int c = 0; c < NS_; c++) { if (sp[c] > 0) nst++; srank[c] = nst - 1; }

    unsigned kb = __ballot_sync(FULL, kept);
    int rank_k = __popc(kb & ((1u << lane) - 1u));
    int rk = __popc(kb);

    float* lut = g_lutf + b * LUTN;
    if (lane < NS_) lut[lane] = (float)(srank[lane] + 1);
    int lv = kept ? (1 + nst + rank_k)
                  : ((semlab < NS_) ? (srank[semlab] + 1) : 0);
    lut[NS_ + lane] = (float)lv;

    if (out_size >= FULL_OUT) {
        float* pcls = out + SEAM_TOT + b * L_;
        float* pisc = out + SEAM_TOT + B_ * L_ + b * L_;
        pcls[lane] = -1.0f;
        if (lane < L_ - 32) pcls[32 + lane] = -1.0f;
        __syncwarp(FULL);
        if (lane == 0) pcls[0] = 255.0f;
        if (lane < NS_ && sp[lane] > 0) pcls[1 + srank[lane]] = (float)lane;
        if (kept) pcls[1 + nst + rank_k] = (float)tmp;
        int vl = 1 + nst + rk;
        pisc[lane] = (lane < vl) ? 0.0f : -1.0f;
        if (lane < L_ - 32) pisc[32 + lane] = ((32 + lane) < vl) ? 0.0f : -1.0f;
        if (lane == 0) out[SEAM_TOT + 2 * B_ * L_ + b] = (float)vl;
    }
    // zero any residual output beyond the defined region (usually empty loop)
    for (int i = FULL_OUT + threadIdx.x; i < out_size; i += 64) out[i] = 0.0f;

    // self-clean scratch for the next graph replay
#pragma unroll
    for (int c = 0; c < C_; c++) hist[c] = 0;
    if (lane < NS_) g_cstuff[b * NS_ + lane] = 0;
}

// ---- kernel 3: LUT remap; shared LUT, 1 quad/thread, 1152 blocks -----------
__global__ void __launch_bounds__(256)
k_out(float* __restrict__ out) {
    __shared__ float lut[B_ * LUTN];
    int t = threadIdx.x;
    if (t < B_ * LUTN) lut[t] = g_lutf[t];
    __syncthreads();
    int i = blockIdx.x * 256 + t;              // quad index
    const int HWQ = HW_ / 4;
    unsigned int p = ((const unsigned int*)g_pp)[i];
    const float* l = lut + ((i >= HWQ) ? LUTN : 0);
    float4 o;
    o.x = l[p & 0xFF];
    o.y = l[(p >> 8) & 0xFF];
    o.z = l[(p >> 16) & 0xFF];
    o.w = l[(p >> 24) & 0xFF];
    ((float4*)out)[i] = o;
}

extern "C" void kernel_launch(void* const* d_in, const int* in_sizes, int n_in,
                              void* d_out, int out_size) {
    const float* sem = nullptr;
    const float* roi = nullptr;
    const float* bbx = nullptr;
    const int*   cls = nullptr;
    for (int i = 0; i < n_in; i++) {
        long long s = in_sizes[i];
        if (s >= 4000000)                 sem = (const float*)d_in[i];
        else if (s >= 100000)             roi = (const float*)d_in[i];
        else if (s >= 512 && s <= 4096)   bbx = (const float*)d_in[i];
        else if (s == 256) { if (!bbx) bbx = (const float*)d_in[i]; }
        else if (s <= 255)                cls = (const int*)d_in[i];
    }
    if (!sem) sem = (const float*)d_in[0];
    if (!roi) roi = (const float*)d_in[1];
    if (!bbx) bbx = (const float*)d_in[2];
    if (!cls) cls = (const int*)d_in[3];

    float* out = (float*)d_out;

    dim3 g1(H_, B_);
    k_main<<<g1, 256>>>(sem, roi, bbx, cls);
    k_post<<<1, 64>>>(cls, out, out_size);
    k_out<<<SEAM_TOT / 4 / 256, 256>>>(out);   // 1152 blocks
}